// round 2
// baseline (speedup 1.0000x reference)
#include <cuda_runtime.h>

#define PP 6
#define NF 10
#define TABLE 7776            // 6^5
#define TABLE4 1944           // 6^5 / 4
#define K4_TOTAL 15116544     // 6^10 / 4

__device__ float g_A[TABLE];
__device__ float g_C[TABLE];
__device__ float g_den;
__device__ float g_num;

__global__ void prep_kernel(const float* __restrict__ X,
                            const float* __restrict__ a,
                            const float* __restrict__ b) {
    __shared__ float h[NF][PP];
    __shared__ float rs[NF];
    int tid = threadIdx.x;
    if (tid < NF * PP) {
        int i = tid / PP;
        float d = a[tid] - X[i];
        float bb = b[tid];
        h[i][tid % PP] = expf(-(d * d) / (2.0f * bb * bb));
    }
    if (tid == 0) g_num = 0.0f;
    __syncthreads();
    if (tid < NF) {
        float s = 0.0f;
        #pragma unroll
        for (int j = 0; j < PP; j++) s += h[tid][j];
        rs[tid] = s;
    }
    __syncthreads();
    if (tid == 0) {
        float d = 1.0f;
        #pragma unroll
        for (int i = 0; i < NF; i++) d *= rs[i];
        g_den = d;
    }
    // Partial-product tables: A over features 0..4, C over features 5..9.
    for (int idx = tid; idx < TABLE; idx += blockDim.x) {
        int t = idx;
        int d4 = t % PP; t /= PP;
        int d3 = t % PP; t /= PP;
        int d2 = t % PP; t /= PP;
        int d1 = t % PP; t /= PP;
        int d0 = t;
        g_A[idx] = h[0][d0] * h[1][d1] * h[2][d2] * h[3][d3] * h[4][d4];
        g_C[idx] = h[5][d0] * h[6][d1] * h[7][d2] * h[8][d3] * h[9][d4];
    }
}

__global__ void __launch_bounds__(256) sum_kernel(const float4* __restrict__ y4) {
    extern __shared__ float smem[];
    float*  sA  = smem;                       // 7776 floats
    float4* sC4 = (float4*)(smem + TABLE);    // 7776 floats as 1944 float4 (16B aligned)

    for (int i = threadIdx.x; i < TABLE; i += blockDim.x) sA[i] = g_A[i];
    const float4* gC4 = (const float4*)g_C;
    for (int i = threadIdx.x; i < TABLE4; i += blockDim.x) sC4[i] = gC4[i];
    __syncthreads();

    float acc = 0.0f;
    int stride = gridDim.x * blockDim.x;
    #pragma unroll 4
    for (int i = blockIdx.x * blockDim.x + threadIdx.x; i < K4_TOTAL; i += stride) {
        float4 yv = __ldg(&y4[i]);
        int hi  = i / TABLE4;                 // same for 1944 consecutive float4s
        int lo4 = i - hi * TABLE4;
        float4 cv = sC4[lo4];                 // LDS.128, consecutive lanes -> conflict-free
        float  w  = sA[hi];                   // warp-uniform broadcast
        acc += w * (yv.x * cv.x + yv.y * cv.y + yv.z * cv.z + yv.w * cv.w);
    }

    // warp reduce
    #pragma unroll
    for (int off = 16; off; off >>= 1)
        acc += __shfl_xor_sync(0xffffffffu, acc, off);

    __shared__ float warp_sums[8];
    int wid = threadIdx.x >> 5;
    int lid = threadIdx.x & 31;
    if (lid == 0) warp_sums[wid] = acc;
    __syncthreads();
    if (wid == 0) {
        float v = (lid < 8) ? warp_sums[lid] : 0.0f;
        #pragma unroll
        for (int off = 4; off; off >>= 1)
            v += __shfl_xor_sync(0xffffffffu, v, off);
        if (lid == 0) atomicAdd(&g_num, v);
    }
}

__global__ void finish_kernel(float* __restrict__ out) {
    out[0] = g_num / g_den;
}

extern "C" void kernel_launch(void* const* d_in, const int* in_sizes, int n_in,
                              void* d_out, int out_size) {
    const float* X = (const float*)d_in[0];
    const float* a = (const float*)d_in[1];
    const float* b = (const float*)d_in[2];
    const float* y = (const float*)d_in[3];
    float* out = (float*)d_out;

    int smem_bytes = 2 * TABLE * (int)sizeof(float);  // 62208 B
    cudaFuncSetAttribute(sum_kernel,
                         cudaFuncAttributeMaxDynamicSharedMemorySize, smem_bytes);

    prep_kernel<<<1, 256>>>(X, a, b);
    sum_kernel<<<444, 256, smem_bytes>>>((const float4*)y);
    finish_kernel<<<1, 1>>>(out);
}